// round 3
// baseline (speedup 1.0000x reference)
#include <cuda_runtime.h>
#include <cuda_fp16.h>
#include <cstdint>

// ============================================================================
// out_i = || P * U(params) * s_i ||^2, 131072 states of dim 256.
// params are batch-invariant -> precompute A = P*U (128x256 complex) once,
// then a real GEMM with fp16 mma.sync (tcgen05 unavailable: harness PTX
// targets compute_103 base, not sm_103a):
//   S = [sr | si]  (131072 x 512 fp32, converted to fp16 on the fly)
//   Wh[n][k] fp16 (256 x 512), n<128: [Ar | -Ai], n>=128: [Ai | Ar]
//   C[m][n] = sum_k S[m][k] Wh[n][k];  out_m = sum_n C[m][n]^2
// ============================================================================

#define NLAYERS 3
#define NQ 8

__device__ __half Wh_global[256 * 512];

// ---------------------------------------------------------------------------
__device__ __forceinline__ uint32_t smem_u32(const void* p) {
    uint32_t a;
    asm("{ .reg .u64 t; cvta.to.shared.u64 t, %1; cvt.u32.u64 %0, t; }"
        : "=r"(a) : "l"(p));
    return a;
}

__device__ __forceinline__ void ldmatrix_x4(uint32_t r[4], uint32_t addr) {
    asm volatile("ldmatrix.sync.aligned.m8n8.x4.shared.b16 {%0,%1,%2,%3}, [%4];"
                 : "=r"(r[0]), "=r"(r[1]), "=r"(r[2]), "=r"(r[3]) : "r"(addr));
}

__device__ __forceinline__ void mma16816(float c[4], const uint32_t a[4],
                                         uint32_t b0, uint32_t b1) {
    asm volatile(
        "mma.sync.aligned.m16n8k16.row.col.f32.f16.f16.f32 "
        "{%0,%1,%2,%3}, {%4,%5,%6,%7}, {%8,%9}, {%0,%1,%2,%3};"
        : "+f"(c[0]), "+f"(c[1]), "+f"(c[2]), "+f"(c[3])
        : "r"(a[0]), "r"(a[1]), "r"(a[2]), "r"(a[3]), "r"(b0), "r"(b1));
}

__device__ __forceinline__ void cp_async16(uint32_t dst, const void* src) {
    asm volatile("cp.async.cg.shared.global [%0], [%1], 16;"
                 :: "r"(dst), "l"(src) : "memory");
}
#define CP_COMMIT() asm volatile("cp.async.commit_group;" ::: "memory")
#define CP_WAIT0()  asm volatile("cp.async.wait_group 0;" ::: "memory")

// ---------------------------------------------------------------------------
// Setup: simulate circuit on the 256 basis states; block k -> column k of U.
// ---------------------------------------------------------------------------
__global__ void build_weights_kernel(const float* __restrict__ params) {
    __shared__ float2 st[256];
    int k = blockIdx.x;
    int t = threadIdx.x;

    st[t] = make_float2(t == k ? 1.0f : 0.0f, 0.0f);

    for (int l = 0; l < NLAYERS; l++) {
        for (int q = 0; q < NQ; q++) {
            const float* pr = params + (l * NQ + q) * 3;
            float hx = 0.5f * pr[0], hy = 0.5f * pr[1], hz = 0.5f * pr[2];
            float cx = cosf(hx), sx = sinf(hx);
            float cy = cosf(hy), sy = sinf(hy);
            float cz = cosf(hz), sz = sinf(hz);
            float m00r =  cy * cx, m00i =  sy * sx;
            float m01r = -sy * cx, m01i = -cy * sx;
            float m10r =  sy * cx, m10i = -cy * sx;
            float m11r =  cy * cx, m11i = -sy * sx;
            float u00r = cz * m00r + sz * m00i, u00i = cz * m00i - sz * m00r;
            float u01r = cz * m01r + sz * m01i, u01i = cz * m01i - sz * m01r;
            float u10r = cz * m10r - sz * m10i, u10i = cz * m10i + sz * m10r;
            float u11r = cz * m11r - sz * m11i, u11i = cz * m11i + sz * m11r;
            int p = 7 - q;  // qubit 0 = MSB of the flat index
            __syncthreads();
            if (t < 128) {
                int lo = t & ((1 << p) - 1);
                int i0 = ((t >> p) << (p + 1)) | lo;
                int i1 = i0 | (1 << p);
                float2 a0 = st[i0], a1 = st[i1];
                float2 n0, n1;
                n0.x = u00r * a0.x - u00i * a0.y + u01r * a1.x - u01i * a1.y;
                n0.y = u00r * a0.y + u00i * a0.x + u01r * a1.y + u01i * a1.x;
                n1.x = u10r * a0.x - u10i * a0.y + u11r * a1.x - u11i * a1.y;
                n1.y = u10r * a0.y + u10i * a0.x + u11r * a1.y + u11i * a1.x;
                st[i0] = n0;
                st[i1] = n1;
            }
        }
        for (int q = 0; q < NQ; q++) {
            int pc = 7 - q;
            int pt = 7 - ((q + 1) & 7);
            __syncthreads();
            if (((t >> pc) & 1) == 1 && ((t >> pt) & 1) == 0) {
                int j = t | (1 << pt);
                float2 tmp = st[t];
                st[t] = st[j];
                st[j] = tmp;
            }
        }
    }
    __syncthreads();
    if (t < 128) {
        float re = st[t].x, im = st[t].y;
        Wh_global[t * 512 + k]               = __float2half_rn(re);
        Wh_global[t * 512 + 256 + k]         = __float2half_rn(-im);
        Wh_global[(128 + t) * 512 + k]       = __float2half_rn(im);
        Wh_global[(128 + t) * 512 + 256 + k] = __float2half_rn(re);
    }
}

// ---------------------------------------------------------------------------
// GEMM kernel: CTA = 128 batch rows x 256 N. 512 threads = 16 warps,
// warp grid 2(M) x 8(N), warp tile 64x32. K = 512 in 8 chunks of 64.
// SMEM per buffer: A 128x64 fp16 (16KB, 128B swizzled rows) at +0,
//                  B 256x64 fp16 (32KB) at +16KB. Two buffers (96KB).
// ---------------------------------------------------------------------------
static constexpr uint32_t BUF_BYTES = 48 * 1024;
static constexpr uint32_t BS_OFF    = 16 * 1024;
static constexpr uint32_t RED_OFF   = 96 * 1024;
static constexpr uint32_t DYN_SMEM  = 96 * 1024 + 512 + 1024;

__global__ void __launch_bounds__(512, 1)
qmm_kernel(const float* __restrict__ sre, const float* __restrict__ sim,
           float* __restrict__ out) {
    extern __shared__ char smem_raw[];
    uint32_t base  = smem_u32(smem_raw);
    uint32_t abase = (base + 1023u) & ~1023u;
    char* a = smem_raw + (abase - base);
    float* red = (float*)(a + RED_OFF);

    const int tid  = threadIdx.x;
    const int wid  = tid >> 5;
    const int lane = tid & 31;
    const int wm   = wid & 1;   // m-half: rows wm*64..+63
    const int wn   = wid >> 1;  // n-slice: cols wn*32..+31

    // ldmatrix per-lane geometry
    const int r  = lane & 7;
    const int q  = lane >> 3;
    const uint32_t xorv = (uint32_t)r << 4;
    const uint32_t ch16 = (uint32_t)(q >> 1) << 4;
    const int rl = ((q & 1) << 3) + r;  // row within 16-row fragment

    uint32_t aRow[4], bRow[2];
    #pragma unroll
    for (int mf = 0; mf < 4; mf++)
        aRow[mf] = abase + (uint32_t)(wm * 64 + mf * 16 + rl) * 128;
    #pragma unroll
    for (int nb = 0; nb < 2; nb++)
        bRow[nb] = abase + BS_OFF + (uint32_t)(wn * 32 + nb * 16 + rl) * 128;

    // A staging-store geometry: i = tid + it*512 -> row = i>>4, f4 = i&15
    // B cp.async geometry:      i = tid + it*512 -> n = i>>3, seg = i&7
    const long tileBase = (long)blockIdx.x * 128;

    float acc[4][4][4];
    #pragma unroll
    for (int mf = 0; mf < 4; mf++)
        #pragma unroll
        for (int nf = 0; nf < 4; nf++)
            #pragma unroll
            for (int i = 0; i < 4; i++) acc[mf][nf][i] = 0.0f;

    float4 av[4];

    // ---- prologue: chunk 0 ----
    {
        const float* src = sre;
        int cb = 0;
        #pragma unroll
        for (int it = 0; it < 4; it++) {
            int i = tid + it * 512;
            int row = i >> 4, f4 = i & 15;
            av[it] = *(const float4*)(src + (tileBase + row) * 256 + cb + f4 * 4);
        }
        #pragma unroll
        for (int it = 0; it < 4; it++) {
            int i = tid + it * 512;
            int n = i >> 3, seg = i & 7;
            uint32_t dst = abase + BS_OFF +
                           (uint32_t)n * 128 +
                           (((uint32_t)seg * 16) ^ (((uint32_t)n & 7) << 4));
            cp_async16(dst, Wh_global + n * 512 + seg * 8);
        }
        CP_COMMIT();
    }

    for (int c = 0; c < 8; c++) {
        const int b = c & 1;
        const uint32_t bufoff = (uint32_t)b * BUF_BYTES;

        // store A (chunk c) into As[b], fp32 -> fp16
        #pragma unroll
        for (int it = 0; it < 4; it++) {
            int i = tid + it * 512;
            int row = i >> 4, f4 = i & 15;
            __half2 p0 = __floats2half2_rn(av[it].x, av[it].y);
            __half2 p1 = __floats2half2_rn(av[it].z, av[it].w);
            uint2 u;
            u.x = *(const uint32_t*)&p0;
            u.y = *(const uint32_t*)&p1;
            uint32_t byte = (uint32_t)row * 128 +
                            (((uint32_t)f4 * 8) ^ (((uint32_t)row & 7) << 4));
            *(uint2*)(a + bufoff + byte) = u;
        }

        CP_WAIT0();           // B (chunk c) arrived
        __syncthreads();      // buffer b fully populated for all warps

        // issue next chunk's loads (overlap with compute below)
        if (c < 7) {
            const int cn = c + 1;
            const float* src = (cn < 4) ? sre : sim;
            int cb = (cn & 3) * 64;
            #pragma unroll
            for (int it = 0; it < 4; it++) {
                int i = tid + it * 512;
                int row = i >> 4, f4 = i & 15;
                av[it] = *(const float4*)(src + (tileBase + row) * 256 + cb + f4 * 4);
            }
            uint32_t nbuf = (uint32_t)(b ^ 1) * BUF_BYTES;
            #pragma unroll
            for (int it = 0; it < 4; it++) {
                int i = tid + it * 512;
                int n = i >> 3, seg = i & 7;
                uint32_t dst = abase + nbuf + BS_OFF +
                               (uint32_t)n * 128 +
                               (((uint32_t)seg * 16) ^ (((uint32_t)n & 7) << 4));
                cp_async16(dst, Wh_global + n * 512 + cn * 64 + seg * 8);
            }
            CP_COMMIT();
        }

        // compute chunk c: 4 k-steps of 16
        #pragma unroll
        for (int ks = 0; ks < 4; ks++) {
            uint32_t cx = (((uint32_t)ks * 32) | ch16) ^ xorv;
            uint32_t af[4][4];
            #pragma unroll
            for (int mf = 0; mf < 4; mf++)
                ldmatrix_x4(af[mf], aRow[mf] + bufoff + cx);
            uint32_t bf[2][4];
            #pragma unroll
            for (int nb = 0; nb < 2; nb++)
                ldmatrix_x4(bf[nb], bRow[nb] + bufoff + cx);
            #pragma unroll
            for (int mf = 0; mf < 4; mf++)
                #pragma unroll
                for (int nf = 0; nf < 4; nf++) {
                    int nb = nf >> 1, sub = nf & 1;
                    mma16816(acc[mf][nf], af[mf], bf[nb][sub], bf[nb][sub + 2]);
                }
        }
    }

    // ---- epilogue: out[m] = sum_n C[m][n]^2 ----
    __syncthreads();
    if (tid < 128) red[tid] = 0.0f;
    __syncthreads();

    #pragma unroll
    for (int mf = 0; mf < 4; mf++) {
        float s_lo = 0.0f, s_hi = 0.0f;
        #pragma unroll
        for (int nf = 0; nf < 4; nf++) {
            s_lo = fmaf(acc[mf][nf][0], acc[mf][nf][0], s_lo);
            s_lo = fmaf(acc[mf][nf][1], acc[mf][nf][1], s_lo);
            s_hi = fmaf(acc[mf][nf][2], acc[mf][nf][2], s_hi);
            s_hi = fmaf(acc[mf][nf][3], acc[mf][nf][3], s_hi);
        }
        // reduce over the 4 lanes of each row group
        s_lo += __shfl_xor_sync(0xFFFFFFFF, s_lo, 1);
        s_lo += __shfl_xor_sync(0xFFFFFFFF, s_lo, 2);
        s_hi += __shfl_xor_sync(0xFFFFFFFF, s_hi, 1);
        s_hi += __shfl_xor_sync(0xFFFFFFFF, s_hi, 2);
        if ((lane & 3) == 0) {
            int row = wm * 64 + mf * 16 + (lane >> 2);
            atomicAdd(red + row, s_lo);
            atomicAdd(red + row + 8, s_hi);
        }
    }
    __syncthreads();
    if (tid < 128) out[tileBase + tid] = red[tid];
}

// ---------------------------------------------------------------------------
extern "C" void kernel_launch(void* const* d_in, const int* in_sizes, int n_in,
                              void* d_out, int out_size) {
    const float* params = (const float*)d_in[0];
    const float* sre    = (const float*)d_in[1];
    const float* sim    = (const float*)d_in[2];
    float* out = (float*)d_out;

    cudaFuncSetAttribute(qmm_kernel, cudaFuncAttributeMaxDynamicSharedMemorySize,
                         DYN_SMEM);

    build_weights_kernel<<<256, 256>>>(params);
    qmm_kernel<<<1024, 512, DYN_SMEM>>>(sre, sim, out);
}